// round 5
// baseline (speedup 1.0000x reference)
#include <cuda_runtime.h>
#include <cuda_fp16.h>
#include <cuda_bf16.h>
#include <cstdint>

#define N_NODES   50000
#define D_FEAT    128
#define OUT_STRIDE 256

// Fixed-stride per-node buckets. Degrees Poisson(16) / Poisson(48);
// overflow probability over 50K nodes ~1e-12 / ~1e-15 — clamped anyway.
#define S1 64
#define S2 128

#define CONV_N      (N_NODES * (D_FEAT / 2))     // 3.2M half2 elements
#define CONV_BLOCKS ((CONV_N + 255) / 256)       // 12500

// ---------------------------------------------------------------------------
// Device scratch (allocation-free; statically zero-initialized at load).
// INVARIANT: g_cnt1/g_cnt2 are all-zero at kernel_launch entry. The gather
// kernel re-zeroes them after use, so every call (correctness, capture,
// replay) sees zeros. Packed pair: (col << 16) | fp16_bits(val).
// ---------------------------------------------------------------------------
__device__ int  g_cnt1[N_NODES];
__device__ int  g_cnt2[N_NODES];
__device__ unsigned g_pairs1[(size_t)N_NODES * S1];
__device__ unsigned g_pairs2[(size_t)N_NODES * S2];
__device__ __align__(16) __half2 g_xh[(size_t)CONV_N];   // fp16 copy of x

// ---------------------------------------------------------------------------
// 1. Fused convert + scatter. Blocks [0, CONV_BLOCKS) convert x to fp16;
//    remaining blocks bucket-scatter both edge lists. Independent roles —
//    counters are already zero (invariant), so no ordering needed.
// ---------------------------------------------------------------------------
__global__ void prep_kernel(const float2* __restrict__ x2,
                            const int* __restrict__ row1,
                            const int* __restrict__ col1,
                            const float* __restrict__ vals1, int n1,
                            const int* __restrict__ row2,
                            const int* __restrict__ col2,
                            const float* __restrict__ vals2, int n2) {
    if (blockIdx.x < CONV_BLOCKS) {
        int i = blockIdx.x * blockDim.x + threadIdx.x;
        if (i < CONV_N) g_xh[i] = __float22half2_rn(__ldg(x2 + i));
        return;
    }
    int e = (blockIdx.x - CONV_BLOCKS) * blockDim.x + threadIdx.x;
    if (e < n1) {
        int r = __ldg(row1 + e);
        int s = atomicAdd(&g_cnt1[r], 1);
        if (s < S1) {
            unsigned hv = __half_as_ushort(__float2half_rn(__ldg(vals1 + e)));
            g_pairs1[(size_t)r * S1 + s] = ((unsigned)__ldg(col1 + e) << 16) | hv;
        }
    } else if (e < n1 + n2) {
        int e2 = e - n1;
        int r = __ldg(row2 + e2);
        int s = atomicAdd(&g_cnt2[r], 1);
        if (s < S2) {
            unsigned hv = __half_as_ushort(__float2half_rn(__ldg(vals2 + e2)));
            g_pairs2[(size_t)r * S2 + s] = ((unsigned)__ldg(col2 + e2) << 16) | hv;
        }
    }
}

// ---------------------------------------------------------------------------
// 2. Warp-per-node gather (fp16 x) + fp32 register accumulate + one store.
//    Lane k owns 4 features (one uint2 = 4 halfs of the x row).
//    4 packed edges fetched per single uniform uint4 load.
//    Resets the node's counter to 0 to restore the invariant.
// ---------------------------------------------------------------------------
__device__ __forceinline__ void fma_h4(float4& acc, uint2 u, unsigned pe,
                                       const uint2* __restrict__ xbase, int lane) {
    (void)xbase; (void)lane;
    float v = __half2float(__ushort_as_half((unsigned short)(pe & 0xFFFFu)));
    float2 f0 = __half22float2(*reinterpret_cast<__half2*>(&u.x));
    float2 f1 = __half22float2(*reinterpret_cast<__half2*>(&u.y));
    acc.x += v * f0.x; acc.y += v * f0.y; acc.z += v * f1.x; acc.w += v * f1.y;
}

__global__ void gather_kernel(float* __restrict__ out) {
    int gw = (blockIdx.x * blockDim.x + threadIdx.x) >> 5;
    if (gw >= 2 * N_NODES) return;
    int lane = threadIdx.x & 31;

    int node, col_off, cnt;
    const unsigned* seg;
    int* cnt_ptr;
    if (gw < N_NODES) {
        node = gw;            col_off = 0;
        seg  = g_pairs1 + (size_t)node * S1;
        cnt_ptr = &g_cnt1[node];
        cnt  = min(*cnt_ptr, S1);
    } else {
        node = gw - N_NODES;  col_off = D_FEAT;
        seg  = g_pairs2 + (size_t)node * S2;
        cnt_ptr = &g_cnt2[node];
        cnt  = min(*cnt_ptr, S2);
    }
    if (lane == 0) *cnt_ptr = 0;   // restore invariant for next call

    const uint2* xbase = reinterpret_cast<const uint2*>(g_xh);
    const uint4* seg4 = reinterpret_cast<const uint4*>(seg);  // 256B-aligned

    float4 acc = make_float4(0.f, 0.f, 0.f, 0.f);
    int i = 0;
    for (; i + 4 <= cnt; i += 4) {
        uint4 p = __ldg(seg4 + (i >> 2));       // 4 packed edges, one load
        uint2 u0 = xbase[(size_t)(p.x >> 16) * 32 + lane];
        uint2 u1 = xbase[(size_t)(p.y >> 16) * 32 + lane];
        uint2 u2 = xbase[(size_t)(p.z >> 16) * 32 + lane];
        uint2 u3 = xbase[(size_t)(p.w >> 16) * 32 + lane];
        fma_h4(acc, u0, p.x, xbase, lane);
        fma_h4(acc, u1, p.y, xbase, lane);
        fma_h4(acc, u2, p.z, xbase, lane);
        fma_h4(acc, u3, p.w, xbase, lane);
    }
    for (; i < cnt; i++) {
        unsigned p = __ldg(seg + i);
        uint2 u = xbase[(size_t)(p >> 16) * 32 + lane];
        fma_h4(acc, u, p, xbase, lane);
    }

    float4* o = reinterpret_cast<float4*>(out + (size_t)node * OUT_STRIDE + col_off) + lane;
    *o = acc;   // single streaming store; also zeros empty nodes
}

// ---------------------------------------------------------------------------
// kernel_launch — inputs: x, row1, col1, vals1, row2, col2, vals2
// ---------------------------------------------------------------------------
extern "C" void kernel_launch(void* const* d_in, const int* in_sizes, int n_in,
                              void* d_out, int out_size) {
    const float* x     = (const float*)d_in[0];
    const int*   row1  = (const int*)  d_in[1];
    const int*   col1  = (const int*)  d_in[2];
    const float* vals1 = (const float*)d_in[3];
    const int*   row2  = (const int*)  d_in[4];
    const int*   col2  = (const int*)  d_in[5];
    const float* vals2 = (const float*)d_in[6];
    float*       out   = (float*)d_out;

    int n1 = in_sizes[1];
    int n2 = in_sizes[4];
    int nE = n1 + n2;

    int scat_blocks = (nE + 255) / 256;
    prep_kernel<<<CONV_BLOCKS + scat_blocks, 256>>>(
        (const float2*)x, row1, col1, vals1, n1, row2, col2, vals2, n2);

    long long threads = (long long)(2 * N_NODES) * 32;
    int blocks = (int)((threads + 255) / 256);
    gather_kernel<<<blocks, 256>>>(out);
}

// round 6
// speedup vs baseline: 1.8711x; 1.8711x over previous
#include <cuda_runtime.h>
#include <cuda_fp16.h>
#include <cuda_bf16.h>
#include <cstdint>

#define N_NODES   50000
#define D_FEAT    128
#define OUT_STRIDE 256

// Fixed-stride per-node buckets. Degrees Poisson(16) / Poisson(48);
// overflow probability over 50K nodes ~1e-12 / ~1e-15 — clamped anyway.
#define S1 64
#define S2 128

#define CONV_N      (N_NODES * (D_FEAT / 2))     // 3.2M half2 elements
#define CONV_BLOCKS ((CONV_N + 255) / 256)       // 12500

// ---------------------------------------------------------------------------
// Device scratch (allocation-free; statically zero-initialized at load).
// INVARIANT: g_cnt1/g_cnt2 are all-zero at kernel_launch entry. The gather
// kernel re-zeroes them after use, so every call (correctness, capture,
// replay) sees zeros. Pair = (col, fp32 val bits).
// ---------------------------------------------------------------------------
__device__ int  g_cnt1[N_NODES];
__device__ int  g_cnt2[N_NODES];
__device__ int2 g_pairs1[(size_t)N_NODES * S1];
__device__ int2 g_pairs2[(size_t)N_NODES * S2];
__device__ __align__(16) __half2 g_xh[(size_t)CONV_N];   // fp16 copy of x

// ---------------------------------------------------------------------------
// 1. Fused convert + scatter. Blocks [0, CONV_BLOCKS) convert x to fp16;
//    remaining blocks bucket-scatter both edge lists. Independent roles —
//    counters are already zero (invariant), so no ordering needed.
// ---------------------------------------------------------------------------
__global__ void prep_kernel(const float2* __restrict__ x2,
                            const int* __restrict__ row1,
                            const int* __restrict__ col1,
                            const float* __restrict__ vals1, int n1,
                            const int* __restrict__ row2,
                            const int* __restrict__ col2,
                            const float* __restrict__ vals2, int n2) {
    if (blockIdx.x < CONV_BLOCKS) {
        int i = blockIdx.x * blockDim.x + threadIdx.x;
        if (i < CONV_N) g_xh[i] = __float22half2_rn(__ldg(x2 + i));
        return;
    }
    int e = (blockIdx.x - CONV_BLOCKS) * blockDim.x + threadIdx.x;
    if (e < n1) {
        int r = __ldg(row1 + e);
        int s = atomicAdd(&g_cnt1[r], 1);
        if (s < S1)
            g_pairs1[(size_t)r * S1 + s] =
                make_int2(__ldg(col1 + e), __float_as_int(__ldg(vals1 + e)));
    } else if (e < n1 + n2) {
        int e2 = e - n1;
        int r = __ldg(row2 + e2);
        int s = atomicAdd(&g_cnt2[r], 1);
        if (s < S2)
            g_pairs2[(size_t)r * S2 + s] =
                make_int2(__ldg(col2 + e2), __float_as_int(__ldg(vals2 + e2)));
    }
}

// ---------------------------------------------------------------------------
// 2. Warp-per-node gather (fp16 x) + fp32 register accumulate + one store.
//    R4-proven structure: 4 INDEPENDENT pair loads per iteration keep the
//    memory pipe full (the R5 single-uint4 variant serialized the chain and
//    tripled runtime). Lane k owns 4 features (one uint2 of the x row).
// ---------------------------------------------------------------------------
__device__ __forceinline__ void fma_h4(float4& acc, uint2 u, float v) {
    float2 f0 = __half22float2(*reinterpret_cast<__half2*>(&u.x));
    float2 f1 = __half22float2(*reinterpret_cast<__half2*>(&u.y));
    acc.x += v * f0.x; acc.y += v * f0.y; acc.z += v * f1.x; acc.w += v * f1.y;
}

__global__ void gather_kernel(float* __restrict__ out) {
    int gw = (blockIdx.x * blockDim.x + threadIdx.x) >> 5;
    if (gw >= 2 * N_NODES) return;
    int lane = threadIdx.x & 31;

    int node, col_off, cnt;
    const int2* seg;
    int* cnt_ptr;
    if (gw < N_NODES) {
        node = gw;            col_off = 0;
        seg  = g_pairs1 + (size_t)node * S1;
        cnt_ptr = &g_cnt1[node];
    } else {
        node = gw - N_NODES;  col_off = D_FEAT;
        seg  = g_pairs2 + (size_t)node * S2;
        cnt_ptr = &g_cnt2[node];
    }
    cnt = min(__ldg(cnt_ptr), (gw < N_NODES) ? S1 : S2);

    const uint2* xbase = reinterpret_cast<const uint2*>(g_xh);

    float4 acc = make_float4(0.f, 0.f, 0.f, 0.f);
    int i = 0;
    // 4 independent pair loads per iteration -> deep MLP on the x gathers
    for (; i + 4 <= cnt; i += 4) {
        int2 p0 = __ldg(seg + i + 0);
        int2 p1 = __ldg(seg + i + 1);
        int2 p2 = __ldg(seg + i + 2);
        int2 p3 = __ldg(seg + i + 3);
        uint2 u0 = xbase[(size_t)p0.x * 32 + lane];
        uint2 u1 = xbase[(size_t)p1.x * 32 + lane];
        uint2 u2 = xbase[(size_t)p2.x * 32 + lane];
        uint2 u3 = xbase[(size_t)p3.x * 32 + lane];
        fma_h4(acc, u0, __int_as_float(p0.y));
        fma_h4(acc, u1, __int_as_float(p1.y));
        fma_h4(acc, u2, __int_as_float(p2.y));
        fma_h4(acc, u3, __int_as_float(p3.y));
    }
    for (; i < cnt; i++) {
        int2 p = __ldg(seg + i);
        uint2 u = xbase[(size_t)p.x * 32 + lane];
        fma_h4(acc, u, __int_as_float(p.y));
    }

    float4* o = reinterpret_cast<float4*>(out + (size_t)node * OUT_STRIDE + col_off) + lane;
    *o = acc;   // single streaming store; also zeros empty nodes

    if (lane == 0) *cnt_ptr = 0;   // restore invariant (after the hot loop)
}

// ---------------------------------------------------------------------------
// kernel_launch — inputs: x, row1, col1, vals1, row2, col2, vals2
// ---------------------------------------------------------------------------
extern "C" void kernel_launch(void* const* d_in, const int* in_sizes, int n_in,
                              void* d_out, int out_size) {
    const float* x     = (const float*)d_in[0];
    const int*   row1  = (const int*)  d_in[1];
    const int*   col1  = (const int*)  d_in[2];
    const float* vals1 = (const float*)d_in[3];
    const int*   row2  = (const int*)  d_in[4];
    const int*   col2  = (const int*)  d_in[5];
    const float* vals2 = (const float*)d_in[6];
    float*       out   = (float*)d_out;

    int n1 = in_sizes[1];
    int n2 = in_sizes[4];
    int nE = n1 + n2;

    int scat_blocks = (nE + 255) / 256;
    prep_kernel<<<CONV_BLOCKS + scat_blocks, 256>>>(
        (const float2*)x, row1, col1, vals1, n1, row2, col2, vals2, n2);

    long long threads = (long long)(2 * N_NODES) * 32;
    int blocks = (int)((threads + 255) / 256);
    gather_kernel<<<blocks, 256>>>(out);
}